// round 10
// baseline (speedup 1.0000x reference)
#include <cuda_runtime.h>
#include <cuda_bf16.h>

#define BATCH 8
#define NPTS  32768
#define NCH   96
#define NSAMP 1024
#define CSZ   8                 // CTAs per batch-cluster
#define NL    (NPTS / CSZ)      // 4096 points per CTA  (idx>>12 == rank)
#define T     512
#define PPT   (NL / T)          // 8 points per thread
#define NPAIR (PPT / 2)         // 4 packed pairs
#define NWARP (T / 32)          // 16 warps
#define SLOTB 24                // mailbox slot bytes: {d,x | y,z | idx,tag}

// Scratch (no device allocation allowed).
__device__ int g_idx[BATCH * NSAMP];

// ---------------- packed f32x2 helpers (per-lane IEEE rn => bit-exact) -----
typedef unsigned long long ull;
__device__ __forceinline__ ull pk(float a, float b) {
    ull r; asm("mov.b64 %0, {%1,%2};" : "=l"(r) : "f"(a), "f"(b)); return r;
}
__device__ __forceinline__ void upk(ull v, float& a, float& b) {
    asm("mov.b64 {%0,%1}, %2;" : "=f"(a), "=f"(b) : "l"(v));
}
__device__ __forceinline__ ull addx2(ull a, ull b) {
    ull r; asm("add.rn.f32x2 %0, %1, %2;" : "=l"(r) : "l"(a), "l"(b)); return r;
}
__device__ __forceinline__ ull mulx2(ull a, ull b) {
    ull r; asm("mul.rn.f32x2 %0, %1, %2;" : "=l"(r) : "l"(a), "l"(b)); return r;
}
__device__ __forceinline__ unsigned su32(const void* p) {
    unsigned r;
    asm("{.reg .u64 t; cvta.to.shared.u64 t, %1; cvt.u32.u64 %0, t;}" : "=r"(r) : "l"(p));
    return r;
}

// ---------------------------------------------------------------------------
// FPS: 4 clusters x 8 CTAs; each cluster runs TWO independent batches in
// lockstep so batch B's compute hides batch A's cross-CTA exchange latency
// (and vice versa). Per-batch logic identical to the proven R7 kernel:
// packed-f32x2 scan, redux argmax (tie -> min index), DSMEM push mailbox
// with fused {idx,tag} release word and tag spin.
// ---------------------------------------------------------------------------
__global__ void __cluster_dims__(CSZ, 1, 1) __launch_bounds__(T, 1)
fps_kernel(const float* __restrict__ xyz,
           float* __restrict__ out_xyz,
           float* __restrict__ out_idxf)
{
    extern __shared__ float smem[];
    float*    sxA  = smem;                        // batch-A coord lookup
    float*    syA  = smem + NL;
    float*    szA  = smem + 2 * NL;
    float*    sxB  = smem + 3 * NL;               // batch-B coord lookup
    float*    syB  = smem + 4 * NL;
    float*    szB  = smem + 5 * NL;
    unsigned* mbA  = (unsigned*)(smem + 6 * NL);  // [2][CSZ] slots of 6 u32
    unsigned* mbB  = mbA + 2 * CSZ * 6;
    unsigned* swdA = mbB + 2 * CSZ * 6;           // per-warp best dist bits (A)
    unsigned* swiA = swdA + NWARP;
    unsigned* swdB = swiA + NWARP;
    unsigned* swiB = swdB + NWARP;

    const int rank = blockIdx.x;                  // cluster rank 0..7
    const int bp   = blockIdx.y;                  // batch pair 0..3
    const int bA   = 2 * bp, bB = 2 * bp + 1;
    const int tid  = threadIdx.x;
    const int lane = tid & 31;
    const int warp = tid >> 5;
    const int base = rank * NL;
    const float* __restrict__ pA = xyz + (size_t)bA * NPTS * 3;
    const float* __restrict__ pB = xyz + (size_t)bB * NPTS * 3;

    // ---- one-time: load 8 pts per batch -> packed regs + smem lookup copy
    ull xA[NPAIR], yA[NPAIR], zA[NPAIR], xB[NPAIR], yB[NPAIR], zB[NPAIR];
    {
        float buf[24];
        const float4* p4 = (const float4*)(pA + (size_t)(base + tid * PPT) * 3);
#pragma unroll
        for (int k = 0; k < 6; k++) ((float4*)buf)[k] = p4[k];
#pragma unroll
        for (int i = 0; i < PPT; i++) {
            sxA[tid * PPT + i] = buf[3 * i];
            syA[tid * PPT + i] = buf[3 * i + 1];
            szA[tid * PPT + i] = buf[3 * i + 2];
        }
#pragma unroll
        for (int q = 0; q < NPAIR; q++) {
            xA[q] = pk(buf[6 * q + 0], buf[6 * q + 3]);
            yA[q] = pk(buf[6 * q + 1], buf[6 * q + 4]);
            zA[q] = pk(buf[6 * q + 2], buf[6 * q + 5]);
        }
        const float4* q4 = (const float4*)(pB + (size_t)(base + tid * PPT) * 3);
#pragma unroll
        for (int k = 0; k < 6; k++) ((float4*)buf)[k] = q4[k];
#pragma unroll
        for (int i = 0; i < PPT; i++) {
            sxB[tid * PPT + i] = buf[3 * i];
            syB[tid * PPT + i] = buf[3 * i + 1];
            szB[tid * PPT + i] = buf[3 * i + 2];
        }
#pragma unroll
        for (int q = 0; q < NPAIR; q++) {
            xB[q] = pk(buf[6 * q + 0], buf[6 * q + 3]);
            yB[q] = pk(buf[6 * q + 1], buf[6 * q + 4]);
            zB[q] = pk(buf[6 * q + 2], buf[6 * q + 5]);
        }
    }

    // ---- init mailbox tags, then one cluster barrier before any push ----
    if (tid < 2 * CSZ) { mbA[tid * 6 + 5] = 0xFFFFFFFFu; mbB[tid * 6 + 5] = 0xFFFFFFFFu; }
    __syncthreads();
    asm volatile("barrier.cluster.arrive.aligned;\n" ::: "memory");
    asm volatile("barrier.cluster.wait.aligned;\n"   ::: "memory");

    const unsigned mbA_u = su32(mbA);
    const unsigned mbB_u = su32(mbB);

    // Producers: warp0 (batch A), warp1 (batch B) — different SMSPs.
    unsigned remA0 = 0, remA1 = 0, remB0 = 0, remB1 = 0;
    if (warp == 0 && lane < CSZ) {
        const unsigned l0 = mbA_u + (unsigned)((0 * CSZ + rank) * SLOTB);
        const unsigned l1 = mbA_u + (unsigned)((1 * CSZ + rank) * SLOTB);
        asm("mapa.shared::cluster.u32 %0, %1, %2;" : "=r"(remA0) : "r"(l0), "r"(lane));
        asm("mapa.shared::cluster.u32 %0, %1, %2;" : "=r"(remA1) : "r"(l1), "r"(lane));
    }
    if (warp == 1 && lane < CSZ) {
        const unsigned l0 = mbB_u + (unsigned)((0 * CSZ + rank) * SLOTB);
        const unsigned l1 = mbB_u + (unsigned)((1 * CSZ + rank) * SLOTB);
        asm("mapa.shared::cluster.u32 %0, %1, %2;" : "=r"(remB0) : "r"(l0), "r"(lane));
        asm("mapa.shared::cluster.u32 %0, %1, %2;" : "=r"(remB1) : "r"(l1), "r"(lane));
    }

    float dA[PPT], dB[PPT];
#pragma unroll
    for (int i = 0; i < PPT; i++) { dA[i] = 1e10f; dB[i] = 1e10f; }

    int   curA = 0, curB = 0;
    float cxA = __ldg(pA + 0), cyA = __ldg(pA + 1), czA = __ldg(pA + 2);
    float cxB = __ldg(pB + 0), cyB = __ldg(pB + 1), czB = __ldg(pB + 2);

    for (int s = 0; s < NSAMP; s++) {
        // Outputs on non-critical warps (state from previous consumer phase).
        if (rank == 0 && warp == 2 && lane == 0) {
            g_idx[bA * NSAMP + s]    = curA;
            out_idxf[bA * NSAMP + s] = (float)curA;
            float* o = out_xyz + ((size_t)bA * NSAMP + s) * 3;
            o[0] = cxA; o[1] = cyA; o[2] = czA;
        }
        if (rank == 0 && warp == 3 && lane == 0) {
            g_idx[bB * NSAMP + s]    = curB;
            out_idxf[bB * NSAMP + s] = (float)curB;
            float* o = out_xyz + ((size_t)bB * NSAMP + s) * 3;
            o[0] = cxB; o[1] = cyB; o[2] = czB;
        }

        // ================= scan + warp reduce, batch A =================
        {
            const ull ncx = pk(-cxA, -cxA), ncy = pk(-cyA, -cyA), ncz = pk(-czA, -czA);
#pragma unroll
            for (int q = 0; q < NPAIR; q++) {
                const ull dx2 = addx2(xA[q], ncx);
                const ull dy2 = addx2(yA[q], ncy);
                const ull dz2 = addx2(zA[q], ncz);
                const ull d2  = addx2(addx2(mulx2(dx2, dx2), mulx2(dy2, dy2)),
                                      mulx2(dz2, dz2));
                float d0, d1; upk(d2, d0, d1);
                dA[2 * q]     = fminf(dA[2 * q],     d0);
                dA[2 * q + 1] = fminf(dA[2 * q + 1], d1);
            }
            const float m01 = fmaxf(dA[0], dA[1]), m23 = fmaxf(dA[2], dA[3]);
            const float m45 = fmaxf(dA[4], dA[5]), m67 = fmaxf(dA[6], dA[7]);
            const float bd  = fmaxf(fmaxf(m01, m23), fmaxf(m45, m67));
            int li = 0;
#pragma unroll
            for (int i = PPT - 1; i >= 0; i--) if (dA[i] == bd) li = i;
            const unsigned bi   = (unsigned)(base + tid * PPT + li);
            const unsigned bdb  = __float_as_uint(bd);
            const unsigned wmax = __reduce_max_sync(0xffffffffu, bdb);
            const unsigned wcnd = (bdb == wmax) ? bi : 0x7fffffffu;
            const unsigned wbi  = __reduce_min_sync(0xffffffffu, wcnd);
            if (lane == 0) { swdA[warp] = wmax; swiA[warp] = wbi; }
        }
        // ================= scan + warp reduce, batch B =================
        {
            const ull ncx = pk(-cxB, -cxB), ncy = pk(-cyB, -cyB), ncz = pk(-czB, -czB);
#pragma unroll
            for (int q = 0; q < NPAIR; q++) {
                const ull dx2 = addx2(xB[q], ncx);
                const ull dy2 = addx2(yB[q], ncy);
                const ull dz2 = addx2(zB[q], ncz);
                const ull d2  = addx2(addx2(mulx2(dx2, dx2), mulx2(dy2, dy2)),
                                      mulx2(dz2, dz2));
                float d0, d1; upk(d2, d0, d1);
                dB[2 * q]     = fminf(dB[2 * q],     d0);
                dB[2 * q + 1] = fminf(dB[2 * q + 1], d1);
            }
            const float m01 = fmaxf(dB[0], dB[1]), m23 = fmaxf(dB[2], dB[3]);
            const float m45 = fmaxf(dB[4], dB[5]), m67 = fmaxf(dB[6], dB[7]);
            const float bd  = fmaxf(fmaxf(m01, m23), fmaxf(m45, m67));
            int li = 0;
#pragma unroll
            for (int i = PPT - 1; i >= 0; i--) if (dB[i] == bd) li = i;
            const unsigned bi   = (unsigned)(base + tid * PPT + li);
            const unsigned bdb  = __float_as_uint(bd);
            const unsigned wmax = __reduce_max_sync(0xffffffffu, bdb);
            const unsigned wcnd = (bdb == wmax) ? bi : 0x7fffffffu;
            const unsigned wbi  = __reduce_min_sync(0xffffffffu, wcnd);
            if (lane == 0) { swdB[warp] = wmax; swiB[warp] = wbi; }
        }
        __syncthreads();

        // ==== producers (parallel on different SMSPs): CTA reduce + push ====
        if (warp == 0) {        // batch A
            const unsigned v = (lane < NWARP) ? swdA[lane] : 0u;
            const unsigned i = (lane < NWARP) ? swiA[lane] : 0x7fffffffu;
            const unsigned cmax = __reduce_max_sync(0xffffffffu, v);
            const unsigned ccnd = (v == cmax) ? i : 0x7fffffffu;
            const unsigned ri   = __reduce_min_sync(0xffffffffu, ccnd);
            const int lj = (int)ri - base;
            const unsigned wx = __float_as_uint(sxA[lj]);
            const unsigned wy = __float_as_uint(syA[lj]);
            const unsigned wz = __float_as_uint(szA[lj]);
            if (lane < CSZ) {
                const unsigned rem = (s & 1) ? remA1 : remA0;
                asm volatile("st.shared::cluster.v2.b32 [%0], {%1,%2};"
                             :: "r"(rem), "r"(cmax), "r"(wx) : "memory");
                asm volatile("st.shared::cluster.v2.b32 [%0], {%1,%2};"
                             :: "r"(rem + 8u), "r"(wy), "r"(wz) : "memory");
                asm volatile("st.release.cluster.shared::cluster.v2.b32 [%0], {%1,%2};"
                             :: "r"(rem + 16u), "r"(ri), "r"((unsigned)s) : "memory");
            }
        }
        if (warp == 1) {        // batch B
            const unsigned v = (lane < NWARP) ? swdB[lane] : 0u;
            const unsigned i = (lane < NWARP) ? swiB[lane] : 0x7fffffffu;
            const unsigned cmax = __reduce_max_sync(0xffffffffu, v);
            const unsigned ccnd = (v == cmax) ? i : 0x7fffffffu;
            const unsigned ri   = __reduce_min_sync(0xffffffffu, ccnd);
            const int lj = (int)ri - base;
            const unsigned wx = __float_as_uint(sxB[lj]);
            const unsigned wy = __float_as_uint(syB[lj]);
            const unsigned wz = __float_as_uint(szB[lj]);
            if (lane < CSZ) {
                const unsigned rem = (s & 1) ? remB1 : remB0;
                asm volatile("st.shared::cluster.v2.b32 [%0], {%1,%2};"
                             :: "r"(rem), "r"(cmax), "r"(wx) : "memory");
                asm volatile("st.shared::cluster.v2.b32 [%0], {%1,%2};"
                             :: "r"(rem + 8u), "r"(wy), "r"(wz) : "memory");
                asm volatile("st.release.cluster.shared::cluster.v2.b32 [%0], {%1,%2};"
                             :: "r"(rem + 16u), "r"(ri), "r"((unsigned)s) : "memory");
            }
        }

        // ==== consumers: batch A then batch B (B's land hidden behind A) ====
        {
            const unsigned slot_a = mbA_u + (unsigned)(((s & 1) * CSZ + lane) * SLOTB);
            unsigned ridx = 0; int ok;
            do {
                unsigned tg = (unsigned)s, ti = 0;
                if (lane < CSZ)
                    asm volatile("ld.acquire.cluster.shared::cta.v2.b32 {%0,%1}, [%2];"
                                 : "=r"(ti), "=r"(tg) : "r"(slot_a + 16u) : "memory");
                ok = __all_sync(0xffffffffu, tg == (unsigned)s);
                ridx = ti;
            } while (!ok);
            unsigned db = 0;
            if (lane < CSZ)
                asm volatile("ld.shared.b32 %0, [%1];" : "=r"(db) : "r"(slot_a) : "memory");
            const unsigned gmax = __reduce_max_sync(0xffffffffu, db);
            const unsigned gcnd = (lane < CSZ && db == gmax) ? ridx : 0x7fffffffu;
            const unsigned wi   = __reduce_min_sync(0xffffffffu, gcnd);
            const unsigned ws   = mbA_u + (unsigned)(((s & 1) * CSZ + (wi >> 12)) * SLOTB);
            unsigned bx, by, bz;
            asm volatile("ld.shared.b32 %0, [%1];" : "=r"(bx) : "r"(ws + 4u) : "memory");
            asm volatile("ld.shared.v2.b32 {%0,%1}, [%2];"
                         : "=r"(by), "=r"(bz) : "r"(ws + 8u) : "memory");
            curA = (int)wi;
            cxA = __uint_as_float(bx); cyA = __uint_as_float(by); czA = __uint_as_float(bz);
        }
        {
            const unsigned slot_a = mbB_u + (unsigned)(((s & 1) * CSZ + lane) * SLOTB);
            unsigned ridx = 0; int ok;
            do {
                unsigned tg = (unsigned)s, ti = 0;
                if (lane < CSZ)
                    asm volatile("ld.acquire.cluster.shared::cta.v2.b32 {%0,%1}, [%2];"
                                 : "=r"(ti), "=r"(tg) : "r"(slot_a + 16u) : "memory");
                ok = __all_sync(0xffffffffu, tg == (unsigned)s);
                ridx = ti;
            } while (!ok);
            unsigned db = 0;
            if (lane < CSZ)
                asm volatile("ld.shared.b32 %0, [%1];" : "=r"(db) : "r"(slot_a) : "memory");
            const unsigned gmax = __reduce_max_sync(0xffffffffu, db);
            const unsigned gcnd = (lane < CSZ && db == gmax) ? ridx : 0x7fffffffu;
            const unsigned wi   = __reduce_min_sync(0xffffffffu, gcnd);
            const unsigned ws   = mbB_u + (unsigned)(((s & 1) * CSZ + (wi >> 12)) * SLOTB);
            unsigned bx, by, bz;
            asm volatile("ld.shared.b32 %0, [%1];" : "=r"(bx) : "r"(ws + 4u) : "memory");
            asm volatile("ld.shared.v2.b32 {%0,%1}, [%2];"
                         : "=r"(by), "=r"(bz) : "r"(ws + 8u) : "memory");
            curB = (int)wi;
            cxB = __uint_as_float(bx); cyB = __uint_as_float(by); czB = __uint_as_float(bz);
        }
    }
}

// ---------------------------------------------------------------------------
// Feature gather: out_fea[b][c][s] = fea[b][c][g_idx[b][s]]
// ---------------------------------------------------------------------------
__global__ void gather_kernel(const float* __restrict__ fea,
                              float* __restrict__ out_fea)
{
    const int t = blockIdx.x * blockDim.x + threadIdx.x;
    if (t >= BATCH * NCH * NSAMP) return;
    const int s = t % NSAMP;
    const int c = (t / NSAMP) % NCH;
    const int b = t / (NCH * NSAMP);
    const int id = g_idx[b * NSAMP + s];
    out_fea[t] = __ldg(fea + ((size_t)b * NCH + c) * NPTS + id);
}

extern "C" void kernel_launch(void* const* d_in, const int* in_sizes, int n_in,
                              void* d_out, int out_size)
{
    const float* xyz = (const float*)d_in[0];   // (B, N, 3)
    const float* fea = (const float*)d_in[1];   // (B, C, N)

    float* out = (float*)d_out;
    // Output layout: new_xyz (B,S,3) | new_fea (B,C,S) | indices-as-float (B,S)
    float* out_xyz  = out;
    float* out_fea  = out + (size_t)BATCH * NSAMP * 3;
    float* out_idxf = out + (size_t)BATCH * NSAMP * 3 + (size_t)BATCH * NCH * NSAMP;

    const int smem_bytes = 6 * NL * 4            // coord lookup copies (2 batches)
                         + 2 * 2 * CSZ * 6 * 4   // mailboxes (2 batches)
                         + 4 * NWARP * 4;        // per-warp reduce scratch
    cudaFuncSetAttribute(fps_kernel, cudaFuncAttributeMaxDynamicSharedMemorySize, smem_bytes);

    fps_kernel<<<dim3(CSZ, BATCH / 2), T, smem_bytes>>>(xyz, out_xyz, out_idxf);

    const int total = BATCH * NCH * NSAMP;
    gather_kernel<<<(total + 255) / 256, 256>>>(fea, out_fea);
}

// round 11
// speedup vs baseline: 1.4750x; 1.4750x over previous
#include <cuda_runtime.h>
#include <cuda_bf16.h>

#define BATCH 8
#define NPTS  32768
#define NCH   96
#define NSAMP 1024
#define CSZ   8                 // CTAs per batch (cluster)
#define NL    (NPTS / CSZ)      // 4096 points per CTA  (idx>>12 == rank)
#define T     256
#define PPT   (NL / T)          // 16 points per thread
#define NPAIR (PPT / 2)         // 8 packed pairs
#define NWARP (T / 32)          // 8 warps
#define SLOTB 24                // mailbox slot bytes: {d,x | y,z | idx,tag}

// Scratch (no device allocation allowed).
__device__ int g_idx[BATCH * NSAMP];

// ---------------- packed f32x2 helpers (per-lane IEEE rn => bit-exact) -----
typedef unsigned long long ull;
__device__ __forceinline__ ull pk(float a, float b) {
    ull r; asm("mov.b64 %0, {%1,%2};" : "=l"(r) : "f"(a), "f"(b)); return r;
}
__device__ __forceinline__ void upk(ull v, float& a, float& b) {
    asm("mov.b64 {%0,%1}, %2;" : "=f"(a), "=f"(b) : "l"(v));
}
__device__ __forceinline__ ull addx2(ull a, ull b) {
    ull r; asm("add.rn.f32x2 %0, %1, %2;" : "=l"(r) : "l"(a), "l"(b)); return r;
}
__device__ __forceinline__ ull mulx2(ull a, ull b) {
    ull r; asm("mul.rn.f32x2 %0, %1, %2;" : "=l"(r) : "l"(a), "l"(b)); return r;
}
__device__ __forceinline__ unsigned su32(const void* p) {
    unsigned r;
    asm("{.reg .u64 t; cvta.to.shared.u64 t, %1; cvt.u32.u64 %0, t;}" : "=r"(r) : "l"(p));
    return r;
}

// ---------------------------------------------------------------------------
// FPS: 8-CTA cluster per batch (R7 structure), 256 threads/CTA. Coords in
// registers (packed f32x2 scan); argmax at all levels via redux.sync
// (dist>=0 => u32-monotonic bits; tie -> min index); DSMEM push mailbox,
// fused {idx,tag} release word, tag spin.
// ---------------------------------------------------------------------------
__global__ void __cluster_dims__(CSZ, 1, 1) __launch_bounds__(T, 1)
fps_kernel(const float* __restrict__ xyz,
           float* __restrict__ out_xyz,
           float* __restrict__ out_idxf)
{
    extern __shared__ float smem[];
    float*    sx   = smem;                        // winner-coord lookup copies
    float*    sy   = smem + NL;
    float*    sz   = smem + 2 * NL;
    unsigned* mb   = (unsigned*)(smem + 3 * NL);  // [2][CSZ] slots of 6 u32
    unsigned* swdi = mb + 2 * CSZ * 6;            // per-warp {distbits, idx} v2

    const int rank = blockIdx.x;
    const int b    = blockIdx.y;
    const int tid  = threadIdx.x;
    const int lane = tid & 31;
    const int warp = tid >> 5;
    const int base = rank * NL;
    const float* __restrict__ p = xyz + (size_t)b * NPTS * 3;

    // ---- one-time: load my 16 points -> packed registers + smem lookup copy
    ull x2[NPAIR], y2[NPAIR], z2[NPAIR];
    {
        float buf[48];
        const float4* p4 = (const float4*)(p + (size_t)(base + tid * PPT) * 3);
#pragma unroll
        for (int k = 0; k < 12; k++) ((float4*)buf)[k] = p4[k];
#pragma unroll
        for (int i = 0; i < PPT; i++) {
            sx[tid * PPT + i] = buf[3 * i];
            sy[tid * PPT + i] = buf[3 * i + 1];
            sz[tid * PPT + i] = buf[3 * i + 2];
        }
#pragma unroll
        for (int q = 0; q < NPAIR; q++) {
            x2[q] = pk(buf[6 * q + 0], buf[6 * q + 3]);
            y2[q] = pk(buf[6 * q + 1], buf[6 * q + 4]);
            z2[q] = pk(buf[6 * q + 2], buf[6 * q + 5]);
        }
    }

    // ---- init mailbox tags (word 5 of each slot), then one cluster barrier
    if (tid < 2 * CSZ) mb[tid * 6 + 5] = 0xFFFFFFFFu;
    __syncthreads();
    asm volatile("barrier.cluster.arrive.aligned;\n" ::: "memory");
    asm volatile("barrier.cluster.wait.aligned;\n"   ::: "memory");

    const unsigned mb_u   = su32(mb);
    const unsigned swdi_u = su32(swdi);

    // Remote slot addresses: warp0 lane r pushes into peer r's slot[parity][rank].
    unsigned rem0 = 0, rem1 = 0;
    if (warp == 0 && lane < CSZ) {
        const unsigned l0 = mb_u + (unsigned)((0 * CSZ + rank) * SLOTB);
        const unsigned l1 = mb_u + (unsigned)((1 * CSZ + rank) * SLOTB);
        asm("mapa.shared::cluster.u32 %0, %1, %2;" : "=r"(rem0) : "r"(l0), "r"(lane));
        asm("mapa.shared::cluster.u32 %0, %1, %2;" : "=r"(rem1) : "r"(l1), "r"(lane));
    }

    float dist[PPT];
#pragma unroll
    for (int i = 0; i < PPT; i++) dist[i] = 1e10f;

    int   cur = 0;
    float cx = __ldg(p + 0), cy = __ldg(p + 1), cz = __ldg(p + 2);

    for (int s = 0; s < NSAMP; s++) {
        // Output writes on a non-critical warp (warp1), state from prev iter.
        if (rank == 0 && warp == 1 && lane == 0) {
            g_idx[b * NSAMP + s]    = cur;
            out_idxf[b * NSAMP + s] = (float)cur;
            float* o = out_xyz + ((size_t)b * NSAMP + s) * 3;
            o[0] = cx; o[1] = cy; o[2] = cz;
        }

        // ---- scan: packed (dx*dx+dy*dy)+dz*dz, rn ordering (bit-match XLA)
        const ull ncx2 = pk(-cx, -cx), ncy2 = pk(-cy, -cy), ncz2 = pk(-cz, -cz);
#pragma unroll
        for (int q = 0; q < NPAIR; q++) {
            const ull dx2 = addx2(x2[q], ncx2);
            const ull dy2 = addx2(y2[q], ncy2);
            const ull dz2 = addx2(z2[q], ncz2);
            const ull d2  = addx2(addx2(mulx2(dx2, dx2), mulx2(dy2, dy2)),
                                  mulx2(dz2, dz2));
            float d0, d1; upk(d2, d0, d1);
            dist[2 * q]     = fminf(dist[2 * q],     d0);
            dist[2 * q + 1] = fminf(dist[2 * q + 1], d1);
        }
        // tree max over 16 dists
        float m = dist[0];
#pragma unroll
        for (int i = 1; i < PPT; i++) m = fmaxf(m, dist[i]);
        const float bd = m;
        int li = 0;
#pragma unroll
        for (int i = PPT - 1; i >= 0; i--) if (dist[i] == bd) li = i;  // first match
        const unsigned bi = (unsigned)(base + tid * PPT + li);

        // ---- warp reduce via redux (dist>=0 => bits monotone; tie -> min idx)
        const unsigned bdb  = __float_as_uint(bd);
        const unsigned wmax = __reduce_max_sync(0xffffffffu, bdb);
        const unsigned wcnd = (bdb == wmax) ? bi : 0x7fffffffu;
        const unsigned wbi  = __reduce_min_sync(0xffffffffu, wcnd);
        if (lane == 0)
            asm volatile("st.shared.v2.b32 [%0], {%1,%2};"
                         :: "r"(swdi_u + (unsigned)(warp * 8)), "r"(wmax), "r"(wbi)
                         : "memory");
        __syncthreads();

        // ---- warp0: CTA reduce (8 warp results) + DSMEM push ----
        if (warp == 0) {
            unsigned v = 0, i = 0x7fffffffu;
            if (lane < NWARP)
                asm volatile("ld.shared.v2.b32 {%0,%1}, [%2];"
                             : "=r"(v), "=r"(i)
                             : "r"(swdi_u + (unsigned)(lane * 8)) : "memory");
            const unsigned cmax = __reduce_max_sync(0xffffffffu, v);
            const unsigned ccnd = (v == cmax) ? i : 0x7fffffffu;
            const unsigned ri   = __reduce_min_sync(0xffffffffu, ccnd);
            const int lj = (int)ri - base;                 // uniform -> LDS broadcast
            const unsigned wx = __float_as_uint(sx[lj]);
            const unsigned wy = __float_as_uint(sy[lj]);
            const unsigned wz = __float_as_uint(sz[lj]);
            if (lane < CSZ) {
                const unsigned rem = (s & 1) ? rem1 : rem0;
                asm volatile("st.shared::cluster.v2.b32 [%0], {%1,%2};"
                             :: "r"(rem), "r"(cmax), "r"(wx) : "memory");
                asm volatile("st.shared::cluster.v2.b32 [%0], {%1,%2};"
                             :: "r"(rem + 8u), "r"(wy), "r"(wz) : "memory");
                asm volatile("st.release.cluster.shared::cluster.v2.b32 [%0], {%1,%2};"
                             :: "r"(rem + 16u), "r"(ri), "r"((unsigned)s) : "memory");
            }
        }

        // ---- every warp: spin on fused {idx,tag} words, redux over 8 CTAs
        const unsigned slot_a = mb_u + (unsigned)(((s & 1) * CSZ + lane) * SLOTB);
        unsigned ridx = 0;
        int ok;
        do {
            unsigned tg = (unsigned)s, ti = 0;
            if (lane < CSZ)
                asm volatile("ld.acquire.cluster.shared::cta.v2.b32 {%0,%1}, [%2];"
                             : "=r"(ti), "=r"(tg) : "r"(slot_a + 16u) : "memory");
            ok = __all_sync(0xffffffffu, tg == (unsigned)s);
            ridx = ti;
        } while (!ok);

        unsigned db = 0;
        if (lane < CSZ)
            asm volatile("ld.shared.b32 %0, [%1];" : "=r"(db) : "r"(slot_a) : "memory");
        const unsigned gmax = __reduce_max_sync(0xffffffffu, db);
        const unsigned gcnd = (lane < CSZ && db == gmax) ? ridx : 0x7fffffffu;
        const unsigned wi   = __reduce_min_sync(0xffffffffu, gcnd);
        const unsigned wslot = mb_u + (unsigned)(((s & 1) * CSZ + (wi >> 12)) * SLOTB);
        unsigned bx, by, bz;                                // uniform -> broadcast LDS
        asm volatile("ld.shared.b32 %0, [%1];" : "=r"(bx) : "r"(wslot + 4u) : "memory");
        asm volatile("ld.shared.v2.b32 {%0,%1}, [%2];"
                     : "=r"(by), "=r"(bz) : "r"(wslot + 8u) : "memory");
        cur = (int)wi;
        cx = __uint_as_float(bx); cy = __uint_as_float(by); cz = __uint_as_float(bz);
    }
}

// ---------------------------------------------------------------------------
// Feature gather: out_fea[b][c][s] = fea[b][c][g_idx[b][s]]
// ---------------------------------------------------------------------------
__global__ void gather_kernel(const float* __restrict__ fea,
                              float* __restrict__ out_fea)
{
    const int t = blockIdx.x * blockDim.x + threadIdx.x;
    if (t >= BATCH * NCH * NSAMP) return;
    const int s = t % NSAMP;
    const int c = (t / NSAMP) % NCH;
    const int b = t / (NCH * NSAMP);
    const int id = g_idx[b * NSAMP + s];
    out_fea[t] = __ldg(fea + ((size_t)b * NCH + c) * NPTS + id);
}

extern "C" void kernel_launch(void* const* d_in, const int* in_sizes, int n_in,
                              void* d_out, int out_size)
{
    const float* xyz = (const float*)d_in[0];   // (B, N, 3)
    const float* fea = (const float*)d_in[1];   // (B, C, N)

    float* out = (float*)d_out;
    // Output layout: new_xyz (B,S,3) | new_fea (B,C,S) | indices-as-float (B,S)
    float* out_xyz  = out;
    float* out_fea  = out + (size_t)BATCH * NSAMP * 3;
    float* out_idxf = out + (size_t)BATCH * NSAMP * 3 + (size_t)BATCH * NCH * NSAMP;

    const int smem_bytes = 3 * NL * 4            // coord lookup copies
                         + 2 * CSZ * 6 * 4       // mailbox slots
                         + NWARP * 8;            // per-warp {d,idx} v2 scratch
    cudaFuncSetAttribute(fps_kernel, cudaFuncAttributeMaxDynamicSharedMemorySize, smem_bytes);

    fps_kernel<<<dim3(CSZ, BATCH), T, smem_bytes>>>(xyz, out_xyz, out_idxf);

    const int total = BATCH * NCH * NSAMP;
    gather_kernel<<<(total + 255) / 256, 256>>>(fea, out_fea);
}